// round 1
// baseline (speedup 1.0000x reference)
#include <cuda_runtime.h>

#define NSTATE (1u << 22)

// one 2x2 rotation butterfly: new = (c*I - i*s*X) * old
__device__ __forceinline__ void gate1(float& r0, float& i0, float& r1, float& i1,
                                      float c, float s)
{
    float nr0 = c * r0 + s * i1;
    float ni0 = c * i0 - s * r1;
    float nr1 = c * r1 + s * i0;
    float ni1 = c * i1 - s * r0;
    r0 = nr0; i0 = ni0; r1 = nr1; i1 = ni1;
}

#define PAD(x) ((x) + ((x) >> 4))

// apply 4 gates on register bits 0..3 of the 16-element register tile,
// using coefficient indices COFF..COFF+3
#define APPLY4(COFF)                                                          \
    _Pragma("unroll")                                                         \
    for (int rb_ = 0; rb_ < 4; ++rb_) {                                       \
        const int st_ = 1 << rb_;                                             \
        _Pragma("unroll")                                                     \
        for (int p_ = 0; p_ < 16; ++p_) {                                     \
            if (!(p_ & st_))                                                  \
                gate1(ar[p_], ai[p_], ar[p_ | st_], ai[p_ | st_],             \
                      C[(COFF) + rb_], S[(COFF) + rb_]);                      \
        }                                                                     \
    }

// ---------------------------------------------------------------------------
// Kernel A: gates on global bits 0..11 (angles angle[10..21]).
// Tile = 4096 contiguous complex. 256 threads x 16 complex each.
// 3 register rounds (bits 0-3, 4-7, 8-11) with shared-memory re-ownership.
// ---------------------------------------------------------------------------
__global__ void __launch_bounds__(256) gateA(const float* __restrict__ xr,
                                             const float* __restrict__ xi,
                                             const float* __restrict__ ang,
                                             float* __restrict__ outr,
                                             float* __restrict__ outi)
{
    __shared__ float sr[4352];  // 4096 + 256 pad
    __shared__ float si[4352];
    const int t = threadIdx.x;
    const unsigned tileBase = (unsigned)blockIdx.x << 12;

    float C[12], S[12];
#pragma unroll
    for (int b = 0; b < 12; ++b) {
        float a = 0.5f * __ldg(ang + (21 - b));   // bit b <-> angle[21-b]
        sincosf(a, &S[b], &C[b]);
    }

    float ar[16], ai[16];

    // ---- Round 1: vary bits 0..3, coalesced global float4 load ----
    {
        const float4* pr = reinterpret_cast<const float4*>(xr + tileBase + t * 16);
        const float4* pi = reinterpret_cast<const float4*>(xi + tileBase + t * 16);
#pragma unroll
        for (int q = 0; q < 4; ++q) {
            float4 vr = pr[q];
            float4 vi = pi[q];
            ar[q * 4 + 0] = vr.x; ar[q * 4 + 1] = vr.y;
            ar[q * 4 + 2] = vr.z; ar[q * 4 + 3] = vr.w;
            ai[q * 4 + 0] = vi.x; ai[q * 4 + 1] = vi.y;
            ai[q * 4 + 2] = vi.z; ai[q * 4 + 3] = vi.w;
        }
    }
    APPLY4(0);
#pragma unroll
    for (int k = 0; k < 16; ++k) {
        int idx = t * 16 + k;
        sr[PAD(idx)] = ar[k];
        si[PAD(idx)] = ai[k];
    }
    __syncthreads();

    // ---- Round 2: vary bits 4..7 ----
#pragma unroll
    for (int j = 0; j < 16; ++j) {
        int idx = (t & 15) | (j << 4) | ((t >> 4) << 8);
        ar[j] = sr[PAD(idx)];
        ai[j] = si[PAD(idx)];
    }
    APPLY4(4);
#pragma unroll
    for (int j = 0; j < 16; ++j) {
        int idx = (t & 15) | (j << 4) | ((t >> 4) << 8);
        sr[PAD(idx)] = ar[j];
        si[PAD(idx)] = ai[j];
    }
    __syncthreads();

    // ---- Round 3: vary bits 8..11, coalesced global store ----
#pragma unroll
    for (int j = 0; j < 16; ++j) {
        int idx = t | (j << 8);
        ar[j] = sr[PAD(idx)];
        ai[j] = si[PAD(idx)];
    }
    APPLY4(8);
#pragma unroll
    for (int j = 0; j < 16; ++j) {
        unsigned g = tileBase + (unsigned)t + ((unsigned)j << 8);
        outr[g] = ar[j];
        outi[g] = ai[j];
    }
}

// ---------------------------------------------------------------------------
// Kernel B: gates on global bits 12..21 (angles angle[0..9]). In-place on out.
// Tile = (8 contiguous, bits 0..2) x (1024 strided, bits 12..21) = 8192 cplx.
// 512 threads x 16 complex. 3 register rounds (h0-3, h4-7, h8-9).
// ---------------------------------------------------------------------------
__global__ void __launch_bounds__(512) gateB(float* __restrict__ dr,
                                             float* __restrict__ di,
                                             const float* __restrict__ ang)
{
    extern __shared__ float sm[];
    float* sr = sm;           // 8704 floats
    float* si = sm + 8704;    // 8704 floats
    const int t = threadIdx.x;
    const unsigned base = (unsigned)blockIdx.x << 3;  // bits 3..11

    float C[10], S[10];
#pragma unroll
    for (int g = 0; g < 10; ++g) {
        float a = 0.5f * __ldg(ang + (9 - g));  // bit 12+g <-> angle[9-g]
        sincosf(a, &S[g], &C[g]);
    }

    // ---- global -> shared (32B sector-granular segments) ----
#pragma unroll
    for (int q = 0; q < 2; ++q) {
        int seg = t + q * 512;                       // hi index 0..1023
        unsigned g = ((unsigned)seg << 12) + base;
        int l = seg << 3;
        float4 r0 = *reinterpret_cast<const float4*>(dr + g);
        float4 r1 = *reinterpret_cast<const float4*>(dr + g + 4);
        float4 m0 = *reinterpret_cast<const float4*>(di + g);
        float4 m1 = *reinterpret_cast<const float4*>(di + g + 4);
        sr[PAD(l + 0)] = r0.x; sr[PAD(l + 1)] = r0.y;
        sr[PAD(l + 2)] = r0.z; sr[PAD(l + 3)] = r0.w;
        sr[PAD(l + 4)] = r1.x; sr[PAD(l + 5)] = r1.y;
        sr[PAD(l + 6)] = r1.z; sr[PAD(l + 7)] = r1.w;
        si[PAD(l + 0)] = m0.x; si[PAD(l + 1)] = m0.y;
        si[PAD(l + 2)] = m0.z; si[PAD(l + 3)] = m0.w;
        si[PAD(l + 4)] = m1.x; si[PAD(l + 5)] = m1.y;
        si[PAD(l + 6)] = m1.z; si[PAD(l + 7)] = m1.w;
    }
    __syncthreads();

    float ar[16], ai[16];

    // ---- Round 1: vary h0..h3 (global bits 12..15) ----
    {
        const int lo = t & 7, hf = t >> 3;  // hf = h4..h9
#pragma unroll
        for (int j = 0; j < 16; ++j) {
            int idx = lo + (((hf << 4) | j) << 3);
            ar[j] = sr[PAD(idx)];
            ai[j] = si[PAD(idx)];
        }
        APPLY4(0);
#pragma unroll
        for (int j = 0; j < 16; ++j) {
            int idx = lo + (((hf << 4) | j) << 3);
            sr[PAD(idx)] = ar[j];
            si[PAD(idx)] = ai[j];
        }
    }
    __syncthreads();

    // ---- Round 2: vary h4..h7 (global bits 16..19) ----
    {
        const int lo = t & 7, hl = (t >> 3) & 15, ht = t >> 7;  // hl=h0..3, ht=h8..9
#pragma unroll
        for (int j = 0; j < 16; ++j) {
            int idx = lo + ((((ht << 8) | (j << 4) | hl)) << 3);
            ar[j] = sr[PAD(idx)];
            ai[j] = si[PAD(idx)];
        }
        APPLY4(4);
#pragma unroll
        for (int j = 0; j < 16; ++j) {
            int idx = lo + ((((ht << 8) | (j << 4) | hl)) << 3);
            sr[PAD(idx)] = ar[j];
            si[PAD(idx)] = ai[j];
        }
    }
    __syncthreads();

    // ---- Round 3: vary h8,h9 (global bits 20,21); h0,h1 passive ----
    {
        const int lo = t & 7, hm = t >> 3;  // hm = h2..h7
#pragma unroll
        for (int j = 0; j < 16; ++j) {
            int j01 = j & 3, j89 = j >> 2;
            int idx = lo + ((((j89 << 8) | (hm << 2) | j01)) << 3);
            ar[j] = sr[PAD(idx)];
            ai[j] = si[PAD(idx)];
        }
        // gates on register bits 2 (global bit 20, coef 8) and 3 (bit 21, coef 9)
#pragma unroll
        for (int rb = 2; rb <= 3; ++rb) {
            const int st = 1 << rb;
#pragma unroll
            for (int p = 0; p < 16; ++p) {
                if (!(p & st))
                    gate1(ar[p], ai[p], ar[p | st], ai[p | st], C[6 + rb], S[6 + rb]);
            }
        }
#pragma unroll
        for (int j = 0; j < 16; ++j) {
            unsigned j01 = j & 3, j89 = (unsigned)j >> 2;
            unsigned hi = (j89 << 8) | ((unsigned)hm << 2) | j01;
            unsigned g = (hi << 12) + base + (unsigned)lo;
            dr[g] = ar[j];
            di[g] = ai[j];
        }
    }
}

extern "C" void kernel_launch(void* const* d_in, const int* in_sizes, int n_in,
                              void* d_out, int out_size)
{
    const float* xr  = (const float*)d_in[0];
    const float* xi  = (const float*)d_in[1];
    const float* ang = (const float*)d_in[2];
    float* outr = (float*)d_out;
    float* outi = outr + NSTATE;

    // Pass 1: gates on bits 0..11 (input -> out, fully coalesced)
    gateA<<<NSTATE / 4096, 256>>>(xr, xi, ang, outr, outi);

    // Pass 2: gates on bits 12..21 (in-place on out)
    const size_t shB = 2 * 8704 * sizeof(float);  // 69632 bytes
    cudaFuncSetAttribute(gateB, cudaFuncAttributeMaxDynamicSharedMemorySize, (int)shB);
    gateB<<<NSTATE / 8192, 512, shB>>>(outr, outi, ang);
}